// round 2
// baseline (speedup 1.0000x reference)
#include <cuda_runtime.h>

// Problem constants
constexpr int BB  = 8;
constexpr int CC  = 512;
constexpr int LL  = 64;
constexpr int NHW = 4096;
constexpr int PPc = 256;

// gain = 1/sqrt(512) for [64,512] convs; 1/sqrt(64)=0.125 for w_o
#define GAIN_IN 0.04419417382415922f
#define GAIN_O  0.125f

// -------- device scratch (static, allowed) --------
__device__ float g_th [BB * LL * NHW];
__device__ float g_ph [BB * LL * NHW];
__device__ float g_gv [BB * LL * NHW];
__device__ float g_lat[BB * NHW * LL];    // written [b][n][c]; read as [b][l][hw]
__device__ float g_sa [BB * CC * NHW];
__device__ float g_enc[BB * LL * NHW];
__device__ float g_lat2[BB * NHW * LL];

// ============================================================
// proj: out[b][o][n] = gain * sum_c W[o][c] * X[b][c][n]
// O = 64 (full), N tile = 128, K(c) chunked by 32.
// grid (32 ntiles, 8 b), 256 threads.
// ============================================================
__global__ __launch_bounds__(256) void proj_kernel(
    const float* __restrict__ X, const float* __restrict__ W,
    float* __restrict__ out, float gain)
{
    __shared__ float Ws[32][68];    // [c_local][o]
    __shared__ float Xs[32][132];   // [c_local][n_local]

    const int tid = threadIdx.x;
    const int b  = blockIdx.y;
    const int n0 = blockIdx.x * 128;
    const int ty = tid >> 4;        // 0..15 -> o group (4 each)
    const int tx = tid & 15;        // 0..15 -> n group (8 each)

    const float* Xb = X + (size_t)b * CC * NHW;

    float acc[4][8];
#pragma unroll
    for (int i = 0; i < 4; i++)
#pragma unroll
        for (int j = 0; j < 8; j++) acc[i][j] = 0.f;

    for (int c0 = 0; c0 < CC; c0 += 32) {
        __syncthreads();
        // load W chunk transposed: Ws[cl][o] = W[o][c0+cl]
        {
            const int o  = tid >> 3;          // 0..31
            const int c4 = (tid & 7) << 2;    // 0,4,..28
#pragma unroll
            for (int p2 = 0; p2 < 2; p2++) {
                const int oo = o + p2 * 32;
                float4 w = *(const float4*)&W[oo * CC + c0 + c4];
                Ws[c4 + 0][oo] = w.x;
                Ws[c4 + 1][oo] = w.y;
                Ws[c4 + 2][oo] = w.z;
                Ws[c4 + 3][oo] = w.w;
            }
        }
        // load X chunk: Xs[cl][nn] = X[b][c0+cl][n0+nn]
        {
            const int nn = (tid & 31) << 2;
#pragma unroll
            for (int p2 = 0; p2 < 4; p2++) {
                const int cl = (tid >> 5) + p2 * 8;
                *(float4*)&Xs[cl][nn] =
                    *(const float4*)&Xb[(size_t)(c0 + cl) * NHW + n0 + nn];
            }
        }
        __syncthreads();

#pragma unroll 8
        for (int cl = 0; cl < 32; cl++) {
            float4 w  = *(float4*)&Ws[cl][ty << 2];
            float4 x0 = *(float4*)&Xs[cl][tx << 3];
            float4 x1 = *(float4*)&Xs[cl][(tx << 3) + 4];
            float wv[4] = {w.x, w.y, w.z, w.w};
            float xv[8] = {x0.x, x0.y, x0.z, x0.w, x1.x, x1.y, x1.z, x1.w};
#pragma unroll
            for (int i = 0; i < 4; i++)
#pragma unroll
                for (int j = 0; j < 8; j++) acc[i][j] += wv[i] * xv[j];
        }
    }

    float* ob = out + (size_t)b * LL * NHW;
#pragma unroll
    for (int i = 0; i < 4; i++) {
        const int o = (ty << 2) + i;
        float4 r0 = make_float4(acc[i][0] * gain, acc[i][1] * gain,
                                acc[i][2] * gain, acc[i][3] * gain);
        float4 r1 = make_float4(acc[i][4] * gain, acc[i][5] * gain,
                                acc[i][6] * gain, acc[i][7] * gain);
        *(float4*)&ob[(size_t)o * NHW + n0 + (tx << 3)]     = r0;
        *(float4*)&ob[(size_t)o * NHW + n0 + (tx << 3) + 4] = r1;
    }
}

// ============================================================
// flash attention: Q,K,V = [b][64c][4096], no scale.
// Block: 128 queries, stream 64-key tiles, online softmax.
// Output O[b][n][c] contiguous (== the torch .view reinterpret).
// grid (32 ntiles, 8 b), 256 threads, dyn smem 102400 B.
// ============================================================
#define FLASH_SMEM 102400
__global__ __launch_bounds__(256, 2) void flash_kernel(
    const float* __restrict__ Q, const float* __restrict__ K,
    const float* __restrict__ V, float* __restrict__ O)
{
    extern __shared__ float smem[];
    float* Qs = smem;                 // [64][128]
    float* Ks = Qs + 64 * 128;        // [64][68]
    float* Vt = Ks + 64 * 68;         // [64m][68c]
    float* Ps = Vt + 64 * 68;         // [128n][68m]

    const int tid = threadIdx.x;
    const int b  = blockIdx.y;
    const int n0 = blockIdx.x * 128;
    const int ty = tid >> 4;          // n group: 8 rows each
    const int tx = tid & 15;          // m/c group: 4 each

    const float* Qb = Q + (size_t)b * LL * NHW;
    const float* Kb = K + (size_t)b * LL * NHW;
    const float* Vb = V + (size_t)b * LL * NHW;

    // load Q tile: Qs[c][nl]
    {
        const int nn = (tid & 31) << 2;
#pragma unroll
        for (int p2 = 0; p2 < 8; p2++) {
            const int c = (tid >> 5) + p2 * 8;
            *(float4*)&Qs[c * 128 + nn] =
                *(const float4*)&Qb[(size_t)c * NHW + n0 + nn];
        }
    }

    float o_acc[8][4];
    float mrun[8], lrun[8];
#pragma unroll
    for (int i = 0; i < 8; i++) {
        mrun[i] = -1e30f;
        lrun[i] = 0.f;
#pragma unroll
        for (int j = 0; j < 4; j++) o_acc[i][j] = 0.f;
    }

    for (int m0 = 0; m0 < NHW; m0 += 64) {
        __syncthreads();   // protect Ks/Vt/Ps from previous iteration readers
        // load K tile: Ks[c][ml]
        {
            const int mm = (tid & 15) << 2;
#pragma unroll
            for (int p2 = 0; p2 < 4; p2++) {
                const int c = (tid >> 4) + p2 * 16;
                *(float4*)&Ks[c * 68 + mm] =
                    *(const float4*)&Kb[(size_t)c * NHW + m0 + mm];
            }
        }
        // load V tile transposed: Vt[ml][c]
        {
            const int mg = (tid & 15) << 2;
#pragma unroll
            for (int p2 = 0; p2 < 4; p2++) {
                const int c = (tid >> 4) + p2 * 16;
                float4 v = *(const float4*)&Vb[(size_t)c * NHW + m0 + mg];
                Vt[(mg + 0) * 68 + c] = v.x;
                Vt[(mg + 1) * 68 + c] = v.y;
                Vt[(mg + 2) * 68 + c] = v.z;
                Vt[(mg + 3) * 68 + c] = v.w;
            }
        }
        __syncthreads();

        // S = Q^T K  (8n x 4m per thread)
        float s[8][4];
#pragma unroll
        for (int i = 0; i < 8; i++)
#pragma unroll
            for (int j = 0; j < 4; j++) s[i][j] = 0.f;

#pragma unroll 8
        for (int c = 0; c < 64; c++) {
            float4 q0 = *(float4*)&Qs[c * 128 + (ty << 3)];
            float4 q1 = *(float4*)&Qs[c * 128 + (ty << 3) + 4];
            float4 k  = *(float4*)&Ks[c * 68 + (tx << 2)];
            float qv[8] = {q0.x, q0.y, q0.z, q0.w, q1.x, q1.y, q1.z, q1.w};
            float kv[4] = {k.x, k.y, k.z, k.w};
#pragma unroll
            for (int i = 0; i < 8; i++)
#pragma unroll
                for (int j = 0; j < 4; j++) s[i][j] += qv[i] * kv[j];
        }

        // online softmax (rows reduce across the 16 tx lanes, width-16 xor)
#pragma unroll
        for (int i = 0; i < 8; i++) {
            float mx = fmaxf(fmaxf(s[i][0], s[i][1]), fmaxf(s[i][2], s[i][3]));
            mx = fmaxf(mx, __shfl_xor_sync(0xffffffffu, mx, 1, 16));
            mx = fmaxf(mx, __shfl_xor_sync(0xffffffffu, mx, 2, 16));
            mx = fmaxf(mx, __shfl_xor_sync(0xffffffffu, mx, 4, 16));
            mx = fmaxf(mx, __shfl_xor_sync(0xffffffffu, mx, 8, 16));
            const float mo = mrun[i];
            const float mn = fmaxf(mo, mx);
            mrun[i] = mn;
            const float esc = __expf(mo - mn);
            float rs = 0.f;
#pragma unroll
            for (int j = 0; j < 4; j++) {
                float p = __expf(s[i][j] - mn);
                s[i][j] = p;
                rs += p;
            }
            rs += __shfl_xor_sync(0xffffffffu, rs, 1, 16);
            rs += __shfl_xor_sync(0xffffffffu, rs, 2, 16);
            rs += __shfl_xor_sync(0xffffffffu, rs, 4, 16);
            rs += __shfl_xor_sync(0xffffffffu, rs, 8, 16);
            lrun[i] = lrun[i] * esc + rs;
#pragma unroll
            for (int j = 0; j < 4; j++) o_acc[i][j] *= esc;
        }

        // store P: Ps[n][m]
#pragma unroll
        for (int i = 0; i < 8; i++) {
            *(float4*)&Ps[((ty << 3) + i) * 68 + (tx << 2)] =
                make_float4(s[i][0], s[i][1], s[i][2], s[i][3]);
        }
        __syncthreads();

        // O += P V^T   (loop m by 4)
#pragma unroll 2
        for (int m = 0; m < 64; m += 4) {
            float4 v0 = *(float4*)&Vt[(m + 0) * 68 + (tx << 2)];
            float4 v1 = *(float4*)&Vt[(m + 1) * 68 + (tx << 2)];
            float4 v2 = *(float4*)&Vt[(m + 2) * 68 + (tx << 2)];
            float4 v3 = *(float4*)&Vt[(m + 3) * 68 + (tx << 2)];
#pragma unroll
            for (int i = 0; i < 8; i++) {
                float4 p = *(float4*)&Ps[((ty << 3) + i) * 68 + m];
                o_acc[i][0] += p.x * v0.x + p.y * v1.x + p.z * v2.x + p.w * v3.x;
                o_acc[i][1] += p.x * v0.y + p.y * v1.y + p.z * v2.y + p.w * v3.y;
                o_acc[i][2] += p.x * v0.z + p.y * v1.z + p.z * v2.z + p.w * v3.z;
                o_acc[i][3] += p.x * v0.w + p.y * v1.w + p.z * v2.w + p.w * v3.w;
            }
        }
    }

    float* Ob = O + (size_t)b * NHW * LL;
#pragma unroll
    for (int i = 0; i < 8; i++) {
        const float inv = 1.f / lrun[i];
        const int n = n0 + (ty << 3) + i;
        *(float4*)&Ob[(size_t)n * LL + (tx << 2)] =
            make_float4(o_acc[i][0] * inv, o_acc[i][1] * inv,
                        o_acc[i][2] * inv, o_acc[i][3] * inv);
    }
}

// ============================================================
// conv_o + residual: out[b][oc][n] = gamma*0.125*sum_l Wo[oc][l]*lat[b][l][n] + add
// grid (32 ntiles, 8 octiles, 8 b), 256 threads, dyn smem 50176 B.
// ============================================================
#define CONV_SMEM 50176
__global__ __launch_bounds__(256) void conv_o_kernel(
    const float* __restrict__ lat, const float* __restrict__ Wo,
    const float* __restrict__ addsrc, const float* __restrict__ gamma,
    float* __restrict__ out)
{
    extern __shared__ float smem[];
    float* Wos = smem;            // [l][oc_local] 64x68
    float* Ls  = Wos + 64 * 68;   // [l][n_local]  64x128

    const int tid = threadIdx.x;
    const int b   = blockIdx.z;
    const int oc0 = blockIdx.y * 64;
    const int n0  = blockIdx.x * 128;
    const int ty = tid >> 4;
    const int tx = tid & 15;

    // load Wo transposed: Wos[l][ocl]
    {
        const int l4 = (tid & 15) << 2;
#pragma unroll
        for (int p2 = 0; p2 < 4; p2++) {
            const int ocl = (tid >> 4) + p2 * 16;
            float4 w = *(const float4*)&Wo[(oc0 + ocl) * LL + l4];
            Wos[(l4 + 0) * 68 + ocl] = w.x;
            Wos[(l4 + 1) * 68 + ocl] = w.y;
            Wos[(l4 + 2) * 68 + ocl] = w.z;
            Wos[(l4 + 3) * 68 + ocl] = w.w;
        }
    }
    // load lat tile: Ls[l][nn]
    {
        const int nn = (tid & 31) << 2;
#pragma unroll
        for (int p2 = 0; p2 < 8; p2++) {
            const int l = (tid >> 5) + p2 * 8;
            *(float4*)&Ls[l * 128 + nn] =
                *(const float4*)&lat[(size_t)b * LL * NHW + (size_t)l * NHW + n0 + nn];
        }
    }
    __syncthreads();

    float acc[4][8];
#pragma unroll
    for (int i = 0; i < 4; i++)
#pragma unroll
        for (int j = 0; j < 8; j++) acc[i][j] = 0.f;

#pragma unroll 8
    for (int l = 0; l < 64; l++) {
        float4 w  = *(float4*)&Wos[l * 68 + (ty << 2)];
        float4 x0 = *(float4*)&Ls[l * 128 + (tx << 3)];
        float4 x1 = *(float4*)&Ls[l * 128 + (tx << 3) + 4];
        float wv[4] = {w.x, w.y, w.z, w.w};
        float xv[8] = {x0.x, x0.y, x0.z, x0.w, x1.x, x1.y, x1.z, x1.w};
#pragma unroll
        for (int i = 0; i < 4; i++)
#pragma unroll
            for (int j = 0; j < 8; j++) acc[i][j] += wv[i] * xv[j];
    }

    const float coeff = gamma[0] * GAIN_O;
#pragma unroll
    for (int i = 0; i < 4; i++) {
        const int oc = oc0 + (ty << 2) + i;
        const size_t base = (size_t)b * CC * NHW + (size_t)oc * NHW + n0 + (tx << 3);
        float4 a0 = *(const float4*)&addsrc[base];
        float4 a1 = *(const float4*)&addsrc[base + 4];
        float4 r0 = make_float4(coeff * acc[i][0] + a0.x, coeff * acc[i][1] + a0.y,
                                coeff * acc[i][2] + a0.z, coeff * acc[i][3] + a0.w);
        float4 r1 = make_float4(coeff * acc[i][4] + a1.x, coeff * acc[i][5] + a1.y,
                                coeff * acc[i][6] + a1.z, coeff * acc[i][7] + a1.w);
        *(float4*)&out[base]     = r0;
        *(float4*)&out[base + 4] = r1;
    }
}

// ============================================================
// MoCA attention: enc [b][64c][4096], concepts [256p][64c].
// score[n][p] = sum_c enc[c][n]*concepts[p][c]; softmax over p;
// out[n][c] = sum_p sm[n][p]*concepts[p][c].  Out [b][n][c].
// grid (64 ntiles, 8 b), 256 threads, dyn smem 223232 B.
// ============================================================
#define MOCA_SMEM 223232
__global__ __launch_bounds__(256) void moca_kernel(
    const float* __restrict__ E, const float* __restrict__ Cpt,
    float* __restrict__ O)
{
    extern __shared__ float smem[];
    float* Ct = smem;               // [64c][260p]
    float* Cs = Ct + 64 * 260;      // [256p][68c]
    float* Es = Cs + 256 * 68;      // [64c][68n]
    float* Pt = Es + 64 * 68;       // [256p][68n]

    const int tid = threadIdx.x;
    const int b  = blockIdx.y;
    const int n0 = blockIdx.x * 64;
    const int ty = tid >> 4;        // n group (4 each)
    const int tx = tid & 15;        // p group (16 each) / c group (4 each)

    // load concepts: Cs[p][c] and transposed Ct[c][p]
    {
        const int c4 = (tid & 15) << 2;
#pragma unroll
        for (int p2 = 0; p2 < 16; p2++) {
            const int p = (tid >> 4) + p2 * 16;
            float4 v = *(const float4*)&Cpt[p * 64 + c4];
            *(float4*)&Cs[p * 68 + c4] = v;
            Ct[(c4 + 0) * 260 + p] = v.x;
            Ct[(c4 + 1) * 260 + p] = v.y;
            Ct[(c4 + 2) * 260 + p] = v.z;
            Ct[(c4 + 3) * 260 + p] = v.w;
        }
    }
    // load enc tile: Es[c][nn]
    {
        const int nn = (tid & 15) << 2;
#pragma unroll
        for (int p2 = 0; p2 < 4; p2++) {
            const int c = (tid >> 4) + p2 * 16;
            *(float4*)&Es[c * 68 + nn] =
                *(const float4*)&E[(size_t)b * LL * NHW + (size_t)c * NHW + n0 + nn];
        }
    }
    __syncthreads();

    // scores: s[4n][16p]
    float s[4][16];
#pragma unroll
    for (int i = 0; i < 4; i++)
#pragma unroll
        for (int j = 0; j < 16; j++) s[i][j] = 0.f;

#pragma unroll 4
    for (int c = 0; c < 64; c++) {
        float4 q = *(float4*)&Es[c * 68 + (ty << 2)];
        float qv[4] = {q.x, q.y, q.z, q.w};
#pragma unroll
        for (int kk = 0; kk < 4; kk++) {
            float4 k = *(float4*)&Ct[c * 260 + (tx << 4) + (kk << 2)];
            float kv[4] = {k.x, k.y, k.z, k.w};
#pragma unroll
            for (int i = 0; i < 4; i++)
#pragma unroll
                for (int w = 0; w < 4; w++) s[i][(kk << 2) + w] += qv[i] * kv[w];
        }
    }

    // softmax over p (16 local x 16 tx lanes), normalize in place
#pragma unroll
    for (int i = 0; i < 4; i++) {
        float mx = -1e30f;
#pragma unroll
        for (int j = 0; j < 16; j++) mx = fmaxf(mx, s[i][j]);
        mx = fmaxf(mx, __shfl_xor_sync(0xffffffffu, mx, 1, 16));
        mx = fmaxf(mx, __shfl_xor_sync(0xffffffffu, mx, 2, 16));
        mx = fmaxf(mx, __shfl_xor_sync(0xffffffffu, mx, 4, 16));
        mx = fmaxf(mx, __shfl_xor_sync(0xffffffffu, mx, 8, 16));
        float rs = 0.f;
#pragma unroll
        for (int j = 0; j < 16; j++) {
            float p = __expf(s[i][j] - mx);
            s[i][j] = p;
            rs += p;
        }
        rs += __shfl_xor_sync(0xffffffffu, rs, 1, 16);
        rs += __shfl_xor_sync(0xffffffffu, rs, 2, 16);
        rs += __shfl_xor_sync(0xffffffffu, rs, 4, 16);
        rs += __shfl_xor_sync(0xffffffffu, rs, 8, 16);
        const float inv = 1.f / rs;
#pragma unroll
        for (int j = 0; j < 16; j++) s[i][j] *= inv;
    }

    // store Pt[p][n] (float4 over n)
#pragma unroll
    for (int pp = 0; pp < 16; pp++) {
        const int p = (tx << 4) + pp;
        *(float4*)&Pt[p * 68 + (ty << 2)] =
            make_float4(s[0][pp], s[1][pp], s[2][pp], s[3][pp]);
    }
    __syncthreads();

    // O[n][c] = sum_p Pt[p][n]*Cs[p][c]
    float o_acc[4][4];
#pragma unroll
    for (int i = 0; i < 4; i++)
#pragma unroll
        for (int j = 0; j < 4; j++) o_acc[i][j] = 0.f;

#pragma unroll 8
    for (int p = 0; p < 256; p++) {
        float4 pr = *(float4*)&Pt[p * 68 + (ty << 2)];
        float4 v  = *(float4*)&Cs[p * 68 + (tx << 2)];
        float pv[4] = {pr.x, pr.y, pr.z, pr.w};
        float vv[4] = {v.x, v.y, v.z, v.w};
#pragma unroll
        for (int i = 0; i < 4; i++)
#pragma unroll
            for (int j = 0; j < 4; j++) o_acc[i][j] += pv[i] * vv[j];
    }

#pragma unroll
    for (int i = 0; i < 4; i++) {
        const int n = n0 + (ty << 2) + i;
        *(float4*)&O[(size_t)b * NHW * LL + (size_t)n * LL + (tx << 2)] =
            make_float4(o_acc[i][0], o_acc[i][1], o_acc[i][2], o_acc[i][3]);
    }
}

// ============================================================
extern "C" void kernel_launch(void* const* d_in, const int* in_sizes, int n_in,
                              void* d_out, int out_size)
{
    (void)in_sizes; (void)n_in; (void)out_size;
    const float* fm         = (const float*)d_in[0];
    const float* concepts   = (const float*)d_in[1];
    const float* w_theta    = (const float*)d_in[2];
    const float* w_phi      = (const float*)d_in[3];
    const float* w_g        = (const float*)d_in[4];
    const float* w_o        = (const float*)d_in[5];
    const float* gamma_sa   = (const float*)d_in[6];
    const float* gamma_moca = (const float*)d_in[7];
    float* out = (float*)d_out;

    float *th, *ph, *gv, *lat, *sa, *enc, *lat2;
    cudaGetSymbolAddress((void**)&th,   g_th);
    cudaGetSymbolAddress((void**)&ph,   g_ph);
    cudaGetSymbolAddress((void**)&gv,   g_gv);
    cudaGetSymbolAddress((void**)&lat,  g_lat);
    cudaGetSymbolAddress((void**)&sa,   g_sa);
    cudaGetSymbolAddress((void**)&enc,  g_enc);
    cudaGetSymbolAddress((void**)&lat2, g_lat2);

    cudaFuncSetAttribute(flash_kernel,  cudaFuncAttributeMaxDynamicSharedMemorySize, FLASH_SMEM);
    cudaFuncSetAttribute(moca_kernel,   cudaFuncAttributeMaxDynamicSharedMemorySize, MOCA_SMEM);
    cudaFuncSetAttribute(conv_o_kernel, cudaFuncAttributeMaxDynamicSharedMemorySize, CONV_SMEM);

    const dim3 pgrid(32, 8);
    // th/ph/g projections
    proj_kernel<<<pgrid, 256>>>(fm, w_theta, th, GAIN_IN);
    proj_kernel<<<pgrid, 256>>>(fm, w_phi,   ph, GAIN_IN);
    proj_kernel<<<pgrid, 256>>>(fm, w_g,     gv, GAIN_IN);
    // self-attention
    flash_kernel<<<dim3(32, 8), 256, FLASH_SMEM>>>(th, ph, gv, lat);
    // sa_out = gamma_sa * conv_o(lat) + feature_map
    conv_o_kernel<<<dim3(32, 8, 8), 256, CONV_SMEM>>>(lat, w_o, fm, gamma_sa, sa);
    // enc projection (shared theta weights)
    proj_kernel<<<pgrid, 256>>>(sa, w_theta, enc, GAIN_IN);
    // concept attention
    moca_kernel<<<dim3(64, 8), 256, MOCA_SMEM>>>(enc, concepts, lat2);
    // out = gamma_moca * conv_o(lat2) + sa_out
    conv_o_kernel<<<dim3(32, 8, 8), 256, CONV_SMEM>>>(lat2, w_o, sa, gamma_moca, out);
}

// round 5
// speedup vs baseline: 1.4906x; 1.4906x over previous
#include <cuda_runtime.h>
#include <cstdint>

constexpr int BB  = 8;
constexpr int CC  = 512;
constexpr int LL  = 64;
constexpr int NHW = 4096;

#define GAIN_IN 0.04419417382415922f
#define GAIN_O  0.125f

// -------- device scratch --------
__device__ float g_qhi[BB * NHW * LL];   // theta proj, [b][n][c], tf32 hi
__device__ float g_qlo[BB * NHW * LL];   // residual lo
__device__ float g_khi[BB * NHW * LL];   // phi proj
__device__ float g_klo[BB * NHW * LL];
__device__ float g_gv [BB * LL * NHW];   // g proj, [b][c][n]
__device__ float g_lat[BB * NHW * LL];   // attn out [b][n][c]
__device__ float g_sa [BB * CC * NHW];
__device__ float g_enc[BB * LL * NHW];
__device__ float g_lat2[BB * NHW * LL];

// single dynamic-smem symbol for the whole TU
extern __shared__ char dyn_smem[];

// ============================================================
// helpers
// ============================================================
__device__ __forceinline__ uint32_t smem_u32(const void* p) {
    uint32_t r;
    asm("{ .reg .u64 t; cvta.to.shared.u64 t, %1; cvt.u32.u64 %0, t; }" : "=r"(r) : "l"(p));
    return r;
}
__device__ __forceinline__ void cp16(uint32_t dst, const void* src) {
    asm volatile("cp.async.cg.shared.global [%0], [%1], 16;" :: "r"(dst), "l"(src));
}
#define CP_COMMIT() asm volatile("cp.async.commit_group;" ::: "memory")
#define CP_WAIT(n)  asm volatile("cp.async.wait_group %0;" :: "n"(n) : "memory")

// m16n8k8 tf32 mma, D/C fp32 in-place accumulate
__device__ __forceinline__ void mma168(float* d, const uint32_t* a, uint32_t b0, uint32_t b1) {
    asm volatile(
        "mma.sync.aligned.m16n8k8.row.col.f32.tf32.tf32.f32 "
        "{%0,%1,%2,%3}, {%4,%5,%6,%7}, {%8,%9}, {%0,%1,%2,%3};"
        : "+f"(d[0]), "+f"(d[1]), "+f"(d[2]), "+f"(d[3])
        : "r"(a[0]), "r"(a[1]), "r"(a[2]), "r"(a[3]), "r"(b0), "r"(b1));
}

// ============================================================
// flash attention via mma.sync tf32
// smem: Qh[128][68], Ql[128][68], then 2 KV slots {Kh,Kl,Vt}[64][68]
// ============================================================
constexpr int PAD = 68;                        // floats per row
constexpr int QTILE_F = 128 * PAD;             // 8704 floats
constexpr int KVROW_F = 64 * PAD;              // 4352 floats
constexpr int OFF_QH = 0;
constexpr int OFF_QL = QTILE_F;
constexpr int OFF_KV = 2 * QTILE_F;            // slot s at OFF_KV + s*3*KVROW_F
constexpr int SLOT_F = 3 * KVROW_F;            // Kh, Kl, Vt
#define FT_SMEM ((2 * QTILE_F + 2 * SLOT_F) * 4)   // 174080 bytes

__device__ __forceinline__ void prefetch_kv(
    uint32_t slot_base, const float* Khi, const float* Klo, const float* Vg,
    int b, int m0, int tid)
{
    const uint32_t kh = slot_base;
    const uint32_t kl = slot_base + KVROW_F * 4;
    const uint32_t vt = slot_base + 2 * KVROW_F * 4;
    const size_t krow0 = (size_t)(b * NHW + m0);
#pragma unroll
    for (int j = 0; j < 8; j++) {
        int idx = j * 128 + tid;          // 0..1023
        int r = idx >> 4, c4 = idx & 15;
        uint32_t doff = (uint32_t)(r * PAD * 4 + c4 * 16);
        size_t ksrc = (krow0 + r) * 64 + c4 * 4;
        cp16(kh + doff, Khi + ksrc);
        cp16(kl + doff, Klo + ksrc);
        cp16(vt + doff, Vg + ((size_t)(b * LL + r)) * NHW + m0 + c4 * 4);
    }
}

__global__ __launch_bounds__(128, 1) void flash_mma_kernel(
    const float* __restrict__ Qhi, const float* __restrict__ Qlo,
    const float* __restrict__ Khi, const float* __restrict__ Klo,
    const float* __restrict__ Vg,  float* __restrict__ Og)
{
    float* smem = (float*)dyn_smem;
    const uint32_t sb = smem_u32(dyn_smem);
    const int tid  = threadIdx.x;
    const int warp = tid >> 5;
    const int lane = tid & 31;
    const int g    = lane >> 2;     // group id (0..7)
    const int tig  = lane & 3;      // thread-in-group
    const int b  = blockIdx.y;
    const int n0 = blockIdx.x * 128;
    const int NT = 64;

    // ---- prologue: Q (hi/lo) + KV tile 0 ----
    {
        const size_t qr0 = (size_t)(b * NHW + n0);
#pragma unroll
        for (int j = 0; j < 16; j++) {
            int idx = j * 128 + tid;        // 0..2047
            int r = idx >> 4, c4 = idx & 15;
            uint32_t doff = (uint32_t)(r * PAD * 4 + c4 * 16);
            size_t src = (qr0 + r) * 64 + c4 * 4;
            cp16(sb + OFF_QH * 4 + doff, Qhi + src);
            cp16(sb + OFF_QL * 4 + doff, Qlo + src);
        }
        prefetch_kv(sb + OFF_KV * 4, Khi, Klo, Vg, b, 0, tid);
        CP_COMMIT();
    }

    const uint32_t* Qh = (const uint32_t*)(smem + OFF_QH);
    const uint32_t* Ql = (const uint32_t*)(smem + OFF_QL);

    float Oa[2][8][4];
    float lsum[2][2];
#pragma unroll
    for (int m = 0; m < 2; m++) {
        lsum[m][0] = 0.f; lsum[m][1] = 0.f;
#pragma unroll
        for (int c = 0; c < 8; c++)
#pragma unroll
            for (int r = 0; r < 4; r++) Oa[m][c][r] = 0.f;
    }

    const int q0 = warp * 32;       // warp's first q row within the tile

    for (int i = 0; i < NT; i++) {
        __syncthreads();            // all warps done with buffer (i+1)&1 contents
        if (i + 1 < NT)
            prefetch_kv(sb + (OFF_KV + ((i + 1) & 1) * SLOT_F) * 4, Khi, Klo, Vg, b, (i + 1) * 64, tid);
        CP_COMMIT();
        if (i + 1 < NT) { CP_WAIT(1); } else { CP_WAIT(0); }
        __syncthreads();            // tile i visible to all

        const float* slot = smem + OFF_KV + (i & 1) * SLOT_F;
        const uint32_t* Kh = (const uint32_t*)slot;
        const uint32_t* Kl = (const uint32_t*)(slot + KVROW_F);
        const uint32_t* Vt = (const uint32_t*)(slot + 2 * KVROW_F);

        // ---- S = Q K^T (3x tf32 split), fragments S[m][n][4] ----
        float S[2][8][4];
#pragma unroll
        for (int m = 0; m < 2; m++)
#pragma unroll
            for (int n = 0; n < 8; n++)
#pragma unroll
                for (int r = 0; r < 4; r++) S[m][n][r] = 0.f;

#pragma unroll
        for (int k = 0; k < 8; k++) {
            uint32_t Ah[2][4], Al[2][4];
#pragma unroll
            for (int m = 0; m < 2; m++) {
                const int qr = q0 + 16 * m;
                Ah[m][0] = Qh[(qr + g) * PAD + 8 * k + tig];
                Ah[m][1] = Qh[(qr + 8 + g) * PAD + 8 * k + tig];
                Ah[m][2] = Qh[(qr + g) * PAD + 8 * k + tig + 4];
                Ah[m][3] = Qh[(qr + 8 + g) * PAD + 8 * k + tig + 4];
                Al[m][0] = Ql[(qr + g) * PAD + 8 * k + tig];
                Al[m][1] = Ql[(qr + 8 + g) * PAD + 8 * k + tig];
                Al[m][2] = Ql[(qr + g) * PAD + 8 * k + tig + 4];
                Al[m][3] = Ql[(qr + 8 + g) * PAD + 8 * k + tig + 4];
            }
#pragma unroll
            for (int n = 0; n < 8; n++) {
                const int krow = 8 * n + g;
                uint32_t bh0 = Kh[krow * PAD + 8 * k + tig];
                uint32_t bh1 = Kh[krow * PAD + 8 * k + tig + 4];
                uint32_t bl0 = Kl[krow * PAD + 8 * k + tig];
                uint32_t bl1 = Kl[krow * PAD + 8 * k + tig + 4];
                mma168(S[0][n], Ah[0], bh0, bh1);
                mma168(S[1][n], Ah[1], bh0, bh1);
                mma168(S[0][n], Ah[0], bl0, bl1);
                mma168(S[1][n], Ah[1], bl0, bl1);
                mma168(S[0][n], Al[0], bh0, bh1);
                mma168(S[1][n], Al[1], bh0, bh1);
            }
        }

        // ---- P = exp(S), accumulate row sums ----
#pragma unroll
        for (int m = 0; m < 2; m++) {
            float s0 = 0.f, s1 = 0.f;
#pragma unroll
            for (int n = 0; n < 8; n++) {
                float p0 = __expf(S[m][n][0]);
                float p1 = __expf(S[m][n][1]);
                float p2 = __expf(S[m][n][2]);
                float p3 = __expf(S[m][n][3]);
                S[m][n][0] = p0; S[m][n][1] = p1;
                S[m][n][2] = p2; S[m][n][3] = p3;
                s0 += p0 + p1; s1 += p2 + p3;
            }
            lsum[m][0] += s0; lsum[m][1] += s1;
        }

        // ---- O += P V : convert D-frag -> A-frag via shuffles ----
        const int base = lane & ~3;
        const int srcA = base | (tig >> 1);
        const int srcB = srcA + 2;
        const bool odd = (tig & 1);
#pragma unroll
        for (int n = 0; n < 8; n++) {       // key chunk = k-dim of PV
            uint32_t Ap[2][4];
#pragma unroll
            for (int m = 0; m < 2; m++) {
                float e0  = __shfl_sync(0xffffffffu, S[m][n][0], srcA);
                float e1  = __shfl_sync(0xffffffffu, S[m][n][1], srcA);
                float e2  = __shfl_sync(0xffffffffu, S[m][n][2], srcA);
                float e3  = __shfl_sync(0xffffffffu, S[m][n][3], srcA);
                float f0  = __shfl_sync(0xffffffffu, S[m][n][0], srcB);
                float f1  = __shfl_sync(0xffffffffu, S[m][n][1], srcB);
                float f2  = __shfl_sync(0xffffffffu, S[m][n][2], srcB);
                float f3  = __shfl_sync(0xffffffffu, S[m][n][3], srcB);
                Ap[m][0] = __float_as_uint(odd ? e1 : e0);
                Ap[m][1] = __float_as_uint(odd ? e3 : e2);
                Ap[m][2] = __float_as_uint(odd ? f1 : f0);
                Ap[m][3] = __float_as_uint(odd ? f3 : f2);
            }
#pragma unroll
            for (int c = 0; c < 8; c++) {
                uint32_t b0 = Vt[(8 * c + g) * PAD + 8 * n + tig];
                uint32_t b1 = Vt[(8 * c + g) * PAD + 8 * n + tig + 4];
                mma168(Oa[0][c], Ap[0], b0, b1);
                mma168(Oa[1][c], Ap[1], b0, b1);
            }
        }
    }

    // ---- epilogue: reduce lsum over tig lanes, normalize, store ----
#pragma unroll
    for (int m = 0; m < 2; m++)
#pragma unroll
        for (int h = 0; h < 2; h++) {
            lsum[m][h] += __shfl_xor_sync(0xffffffffu, lsum[m][h], 1);
            lsum[m][h] += __shfl_xor_sync(0xffffffffu, lsum[m][h], 2);
            lsum[m][h] = 1.f / lsum[m][h];
        }

#pragma unroll
    for (int m = 0; m < 2; m++) {
        const int r0 = n0 + q0 + 16 * m + g;
#pragma unroll
        for (int c = 0; c < 8; c++) {
            float2 v0 = make_float2(Oa[m][c][0] * lsum[m][0], Oa[m][c][1] * lsum[m][0]);
            float2 v1 = make_float2(Oa[m][c][2] * lsum[m][1], Oa[m][c][3] * lsum[m][1]);
            *(float2*)&Og[((size_t)(b * NHW) + r0)     * 64 + 8 * c + 2 * tig] = v0;
            *(float2*)&Og[((size_t)(b * NHW) + r0 + 8) * 64 + 8 * c + 2 * tig] = v1;
        }
    }
}

// ============================================================
// proj: out[b][o][n] = gain * sum_c W[o][c] * X[b][c][n]
// mode 0: write [b][o][n].  mode 1: hi/lo tf32 split, transposed [b][n][o].
// ============================================================
__global__ __launch_bounds__(256) void proj_kernel(
    const float* __restrict__ X, const float* __restrict__ W,
    float* __restrict__ out, float* __restrict__ olo, int mode, float gain)
{
    __shared__ float Ws[32][68];
    __shared__ float Xs[32][132];

    const int tid = threadIdx.x;
    const int b  = blockIdx.y;
    const int n0 = blockIdx.x * 128;
    const int ty = tid >> 4;
    const int tx = tid & 15;
    const float* Xb = X + (size_t)b * CC * NHW;

    float acc[4][8];
#pragma unroll
    for (int i = 0; i < 4; i++)
#pragma unroll
        for (int j = 0; j < 8; j++) acc[i][j] = 0.f;

    for (int c0 = 0; c0 < CC; c0 += 32) {
        __syncthreads();
        {
            const int o  = tid >> 3;
            const int c4 = (tid & 7) << 2;
#pragma unroll
            for (int p2 = 0; p2 < 2; p2++) {
                const int oo = o + p2 * 32;
                float4 w = *(const float4*)&W[oo * CC + c0 + c4];
                Ws[c4 + 0][oo] = w.x; Ws[c4 + 1][oo] = w.y;
                Ws[c4 + 2][oo] = w.z; Ws[c4 + 3][oo] = w.w;
            }
        }
        {
            const int nn = (tid & 31) << 2;
#pragma unroll
            for (int p2 = 0; p2 < 4; p2++) {
                const int cl = (tid >> 5) + p2 * 8;
                *(float4*)&Xs[cl][nn] = *(const float4*)&Xb[(size_t)(c0 + cl) * NHW + n0 + nn];
            }
        }
        __syncthreads();
#pragma unroll 8
        for (int cl = 0; cl < 32; cl++) {
            float4 w  = *(float4*)&Ws[cl][ty << 2];
            float4 x0 = *(float4*)&Xs[cl][tx << 3];
            float4 x1 = *(float4*)&Xs[cl][(tx << 3) + 4];
            float wv[4] = {w.x, w.y, w.z, w.w};
            float xv[8] = {x0.x, x0.y, x0.z, x0.w, x1.x, x1.y, x1.z, x1.w};
#pragma unroll
            for (int i = 0; i < 4; i++)
#pragma unroll
                for (int j = 0; j < 8; j++) acc[i][j] += wv[i] * xv[j];
        }
    }

    if (mode == 0) {
        float* ob = out + (size_t)b * LL * NHW;
#pragma unroll
        for (int i = 0; i < 4; i++) {
            const int o = (ty << 2) + i;
            float4 r0 = make_float4(acc[i][0]*gain, acc[i][1]*gain, acc[i][2]*gain, acc[i][3]*gain);
            float4 r1 = make_float4(acc[i][4]*gain, acc[i][5]*gain, acc[i][6]*gain, acc[i][7]*gain);
            *(float4*)&ob[(size_t)o * NHW + n0 + (tx << 3)]     = r0;
            *(float4*)&ob[(size_t)o * NHW + n0 + (tx << 3) + 4] = r1;
        }
    } else {
#pragma unroll
        for (int i = 0; i < 4; i++) {
            const int o = (ty << 2) + i;
#pragma unroll
            for (int j = 0; j < 8; j++) {
                const int n = n0 + (tx << 3) + j;
                float v = acc[i][j] * gain;
                float hi;
                asm("cvt.rna.tf32.f32 %0, %1;" : "=f"(hi) : "f"(v));
                out[((size_t)(b * NHW + n)) * 64 + o] = hi;
                olo[((size_t)(b * NHW + n)) * 64 + o] = v - hi;
            }
        }
    }
}

// ============================================================
// conv_o + residual
// ============================================================
#define CONV_SMEM 50176
__global__ __launch_bounds__(256) void conv_o_kernel(
    const float* __restrict__ lat, const float* __restrict__ Wo,
    const float* __restrict__ addsrc, const float* __restrict__ gamma,
    float* __restrict__ out)
{
    float* smem = (float*)dyn_smem;
    float* Wos = smem;
    float* Ls  = Wos + 64 * 68;

    const int tid = threadIdx.x;
    const int b   = blockIdx.z;
    const int oc0 = blockIdx.y * 64;
    const int n0  = blockIdx.x * 128;
    const int ty = tid >> 4;
    const int tx = tid & 15;

    {
        const int l4 = (tid & 15) << 2;
#pragma unroll
        for (int p2 = 0; p2 < 4; p2++) {
            const int ocl = (tid >> 4) + p2 * 16;
            float4 w = *(const float4*)&Wo[(oc0 + ocl) * LL + l4];
            Wos[(l4 + 0) * 68 + ocl] = w.x; Wos[(l4 + 1) * 68 + ocl] = w.y;
            Wos[(l4 + 2) * 68 + ocl] = w.z; Wos[(l4 + 3) * 68 + ocl] = w.w;
        }
    }
    {
        const int nn = (tid & 31) << 2;
#pragma unroll
        for (int p2 = 0; p2 < 8; p2++) {
            const int l = (tid >> 5) + p2 * 8;
            *(float4*)&Ls[l * 128 + nn] =
                *(const float4*)&lat[(size_t)b * LL * NHW + (size_t)l * NHW + n0 + nn];
        }
    }
    __syncthreads();

    float acc[4][8];
#pragma unroll
    for (int i = 0; i < 4; i++)
#pragma unroll
        for (int j = 0; j < 8; j++) acc[i][j] = 0.f;

#pragma unroll 8
    for (int l = 0; l < 64; l++) {
        float4 w  = *(float4*)&Wos[l * 68 + (ty << 2)];
        float4 x0 = *(float4*)&Ls[l * 128 + (tx << 3)];
        float4 x1 = *(float4*)&Ls[l * 128 + (tx << 3) + 4];
        float wv[4] = {w.x, w.y, w.z, w.w};
        float xv[8] = {x0.x, x0.y, x0.z, x0.w, x1.x, x1.y, x1.z, x1.w};
#pragma unroll
        for (int i = 0; i < 4; i++)
#pragma unroll
            for (int j = 0; j < 8; j++) acc[i][j] += wv[i] * xv[j];
    }

    const float coeff = gamma[0] * GAIN_O;
#pragma unroll
    for (int i = 0; i < 4; i++) {
        const int oc = oc0 + (ty << 2) + i;
        const size_t base = (size_t)b * CC * NHW + (size_t)oc * NHW + n0 + (tx << 3);
        float4 a0 = *(const float4*)&addsrc[base];
        float4 a1 = *(const float4*)&addsrc[base + 4];
        *(float4*)&out[base] = make_float4(coeff*acc[i][0]+a0.x, coeff*acc[i][1]+a0.y,
                                           coeff*acc[i][2]+a0.z, coeff*acc[i][3]+a0.w);
        *(float4*)&out[base + 4] = make_float4(coeff*acc[i][4]+a1.x, coeff*acc[i][5]+a1.y,
                                               coeff*acc[i][6]+a1.z, coeff*acc[i][7]+a1.w);
    }
}

// ============================================================
// MoCA attention
// ============================================================
#define MOCA_SMEM 223232
__global__ __launch_bounds__(256) void moca_kernel(
    const float* __restrict__ E, const float* __restrict__ Cpt, float* __restrict__ O)
{
    float* smem = (float*)dyn_smem;
    float* Ct = smem;
    float* Cs = Ct + 64 * 260;
    float* Es = Cs + 256 * 68;
    float* Pt = Es + 64 * 68;

    const int tid = threadIdx.x;
    const int b  = blockIdx.y;
    const int n0 = blockIdx.x * 64;
    const int ty = tid >> 4;
    const int tx = tid & 15;

    {
        const int c4 = (tid & 15) << 2;
#pragma unroll
        for (int p2 = 0; p2 < 16; p2++) {
            const int p = (tid >> 4) + p2 * 16;
            float4 v = *(const float4*)&Cpt[p * 64 + c4];
            *(float4*)&Cs[p * 68 + c4] = v;
            Ct[(c4 + 0) * 260 + p] = v.x; Ct[(c4 + 1) * 260 + p] = v.y;
            Ct[(c4 + 2) * 260 + p] = v.z; Ct[(c4 + 3) * 260 + p] = v.w;
        }
    }
    {
        const int nn = (tid & 15) << 2;
#pragma unroll
        for (int p2 = 0; p2 < 4; p2++) {
            const int c = (tid >> 4) + p2 * 16;
            *(float4*)&Es[c * 68 + nn] =
                *(const float4*)&E[(size_t)b * LL * NHW + (size_t)c * NHW + n0 + nn];
        }
    }
    __syncthreads();

    float s[4][16];
#pragma unroll
    for (int i = 0; i < 4; i++)
#pragma unroll
        for (int j = 0; j < 16; j++) s[i][j] = 0.f;

#pragma unroll 4
    for (int c = 0; c < 64; c++) {
        float4 q = *(float4*)&Es[c * 68 + (ty << 2)];
        float qv[4] = {q.x, q.y, q.z, q.w};
#pragma unroll
        for (int kk = 0; kk < 4; kk++) {
            float4 k = *(float4*)&Ct[c * 260 + (tx << 4) + (kk << 2)];
            float kv[4] = {k.x, k.y, k.z, k.w};
#pragma unroll
            for (int i = 0; i < 4; i++)
#pragma unroll
                for (int w = 0; w < 4; w++) s[i][(kk << 2) + w] += qv[i] * kv[w];
        }
    }

#pragma unroll
    for (int i = 0; i < 4; i++) {
        float mx = -1e30f;
#pragma unroll
        for (int j = 0; j < 16; j++) mx = fmaxf(mx, s[i][j]);
        mx = fmaxf(mx, __shfl_xor_sync(0xffffffffu, mx, 1, 16));
        mx = fmaxf(mx, __shfl_xor_sync(0xffffffffu, mx, 2, 16));
        mx = fmaxf(mx, __shfl_xor_sync(0xffffffffu, mx, 4, 16));
        mx = fmaxf(mx, __shfl_xor_sync(0xffffffffu, mx, 8, 16));
        float rs = 0.f;
#pragma unroll
        for (int j = 0; j < 16; j++) { float p = __expf(s[i][j] - mx); s[i][j] = p; rs += p; }
        rs += __shfl_xor_sync(0xffffffffu, rs, 1, 16);
        rs += __shfl_xor_sync(0xffffffffu, rs, 2, 16);
        rs += __shfl_xor_sync(0xffffffffu, rs, 4, 16);
        rs += __shfl_xor_sync(0xffffffffu, rs, 8, 16);
        const float inv = 1.f / rs;
#pragma unroll
        for (int j = 0; j < 16; j++) s[i][j] *= inv;
    }

#pragma unroll
    for (int pp = 0; pp < 16; pp++) {
        const int p = (tx << 4) + pp;
        *(float4*)&Pt[p * 68 + (ty << 2)] = make_float4(s[0][pp], s[1][pp], s[2][pp], s[3][pp]);
    }
    __syncthreads();

    float o_acc[4][4];
#pragma unroll
    for (int i = 0; i < 4; i++)
#pragma unroll
        for (int j = 0; j < 4; j++) o_acc[i][j] = 0.f;

#pragma unroll 8
    for (int p = 0; p < 256; p++) {
        float4 pr = *(float4*)&Pt[p * 68 + (ty << 2)];
        float4 v  = *(float4*)&Cs[p * 68 + (tx << 2)];
        float pv[4] = {pr.x, pr.y, pr.z, pr.w};
        float vv[4] = {v.x, v.y, v.z, v.w};
#pragma unroll
        for (int i = 0; i < 4; i++)
#pragma unroll
            for (int j = 0; j < 4; j++) o_acc[i][j] += pv[i] * vv[j];
    }
#pragma unroll
    for (int i = 0; i < 4; i++) {
        const int n = n0 + (ty << 2) + i;
        *(float4*)&O[(size_t)b * NHW * LL + (size_t)n * LL + (tx << 2)] =
            make_float4(o_acc[i][0], o_acc[i][1], o_acc[i][2], o_acc[i][3]);
    }
}

// ============================================================
extern "C" void kernel_launch(void* const* d_in, const int* in_sizes, int n_in,
                              void* d_out, int out_size)
{
    (void)in_sizes; (void)n_in; (void)out_size;
    const float* fm         = (const float*)d_in[0];
    const float* concepts   = (const float*)d_in[1];
    const float* w_theta    = (const float*)d_in[2];
    const float* w_phi      = (const float*)d_in[3];
    const float* w_g        = (const float*)d_in[4];
    const float* w_o        = (const float*)d_in[5];
    const float* gamma_sa   = (const float*)d_in[6];
    const float* gamma_moca = (const float*)d_in[7];
    float* out = (float*)d_out;

    float *qhi, *qlo, *khi, *klo, *gv, *lat, *sa, *enc, *lat2;
    cudaGetSymbolAddress((void**)&qhi, g_qhi);
    cudaGetSymbolAddress((void**)&qlo, g_qlo);
    cudaGetSymbolAddress((void**)&khi, g_khi);
    cudaGetSymbolAddress((void**)&klo, g_klo);
    cudaGetSymbolAddress((void**)&gv,  g_gv);
    cudaGetSymbolAddress((void**)&lat, g_lat);
    cudaGetSymbolAddress((void**)&sa,  g_sa);
    cudaGetSymbolAddress((void**)&enc, g_enc);
    cudaGetSymbolAddress((void**)&lat2, g_lat2);

    cudaFuncSetAttribute(flash_mma_kernel, cudaFuncAttributeMaxDynamicSharedMemorySize, FT_SMEM);
    cudaFuncSetAttribute(moca_kernel,      cudaFuncAttributeMaxDynamicSharedMemorySize, MOCA_SMEM);
    cudaFuncSetAttribute(conv_o_kernel,    cudaFuncAttributeMaxDynamicSharedMemorySize, CONV_SMEM);

    const dim3 pgrid(32, 8);
    proj_kernel<<<pgrid, 256>>>(fm, w_theta, qhi, qlo, 1, GAIN_IN);
    proj_kernel<<<pgrid, 256>>>(fm, w_phi,   khi, klo, 1, GAIN_IN);
    proj_kernel<<<pgrid, 256>>>(fm, w_g,     gv,  nullptr, 0, GAIN_IN);
    flash_mma_kernel<<<dim3(32, 8), 128, FT_SMEM>>>(qhi, qlo, khi, klo, gv, lat);
    conv_o_kernel<<<dim3(32, 8, 8), 256, CONV_SMEM>>>(lat, w_o, fm, gamma_sa, sa);
    proj_kernel<<<pgrid, 256>>>(sa, w_theta, enc, nullptr, 0, GAIN_IN);
    moca_kernel<<<dim3(64, 8), 256, MOCA_SMEM>>>(enc, concepts, lat2);
    conv_o_kernel<<<dim3(32, 8, 8), 256, CONV_SMEM>>>(lat2, w_o, sa, gamma_moca, out);
}

// round 6
// speedup vs baseline: 1.9822x; 1.3298x over previous
#include <cuda_runtime.h>
#include <cstdint>

constexpr int BB  = 8;
constexpr int CC  = 512;
constexpr int LL  = 64;
constexpr int NHW = 4096;

#define GAIN_IN 0.04419417382415922f
#define GAIN_O  0.125f

// -------- device scratch --------
__device__ float g_qhi[BB * NHW * LL];   // theta proj, [b][n][c], tf32 hi
__device__ float g_qlo[BB * NHW * LL];
__device__ float g_khi[BB * NHW * LL];
__device__ float g_klo[BB * NHW * LL];
__device__ float g_gv [BB * LL * NHW];   // g proj, [b][c][n]
__device__ float g_lat[BB * NHW * LL];
__device__ float g_sa [BB * CC * NHW];
__device__ float g_enc[BB * LL * NHW];
__device__ float g_lat2[BB * NHW * LL];

extern __shared__ char dyn_smem[];

// ============================================================
// helpers
// ============================================================
__device__ __forceinline__ uint32_t smem_u32(const void* p) {
    uint32_t r;
    asm("{ .reg .u64 t; cvta.to.shared.u64 t, %1; cvt.u32.u64 %0, t; }" : "=r"(r) : "l"(p));
    return r;
}
__device__ __forceinline__ void cp16(uint32_t dst, const void* src) {
    asm volatile("cp.async.cg.shared.global [%0], [%1], 16;" :: "r"(dst), "l"(src));
}
#define CP_COMMIT() asm volatile("cp.async.commit_group;" ::: "memory")
#define CP_WAIT(n)  asm volatile("cp.async.wait_group %0;" :: "n"(n) : "memory")

__device__ __forceinline__ float tf32hi(float v) {
    float h;
    asm("cvt.rna.tf32.f32 %0, %1;" : "=f"(h) : "f"(v));
    return h;
}
// m16n8k8 tf32 mma, fp32 accumulate in place
__device__ __forceinline__ void mma168(float* d, const uint32_t* a, uint32_t b0, uint32_t b1) {
    asm volatile(
        "mma.sync.aligned.m16n8k8.row.col.f32.tf32.tf32.f32 "
        "{%0,%1,%2,%3}, {%4,%5,%6,%7}, {%8,%9}, {%0,%1,%2,%3};"
        : "+f"(d[0]), "+f"(d[1]), "+f"(d[2]), "+f"(d[3])
        : "r"(a[0]), "r"(a[1]), "r"(a[2]), "r"(a[3]), "r"(b0), "r"(b1));
}

// ============================================================
// flash attention via mma.sync tf32 (UNCHANGED from R5 — verified)
// ============================================================
constexpr int PAD = 68;
constexpr int QTILE_F = 128 * PAD;
constexpr int KVROW_F = 64 * PAD;
constexpr int OFF_QH = 0;
constexpr int OFF_QL = QTILE_F;
constexpr int OFF_KV = 2 * QTILE_F;
constexpr int SLOT_F = 3 * KVROW_F;
#define FT_SMEM ((2 * QTILE_F + 2 * SLOT_F) * 4)

__device__ __forceinline__ void prefetch_kv(
    uint32_t slot_base, const float* Khi, const float* Klo, const float* Vg,
    int b, int m0, int tid)
{
    const uint32_t kh = slot_base;
    const uint32_t kl = slot_base + KVROW_F * 4;
    const uint32_t vt = slot_base + 2 * KVROW_F * 4;
    const size_t krow0 = (size_t)(b * NHW + m0);
#pragma unroll
    for (int j = 0; j < 8; j++) {
        int idx = j * 128 + tid;
        int r = idx >> 4, c4 = idx & 15;
        uint32_t doff = (uint32_t)(r * PAD * 4 + c4 * 16);
        size_t ksrc = (krow0 + r) * 64 + c4 * 4;
        cp16(kh + doff, Khi + ksrc);
        cp16(kl + doff, Klo + ksrc);
        cp16(vt + doff, Vg + ((size_t)(b * LL + r)) * NHW + m0 + c4 * 4);
    }
}

__global__ __launch_bounds__(128, 1) void flash_mma_kernel(
    const float* __restrict__ Qhi, const float* __restrict__ Qlo,
    const float* __restrict__ Khi, const float* __restrict__ Klo,
    const float* __restrict__ Vg,  float* __restrict__ Og)
{
    float* smem = (float*)dyn_smem;
    const uint32_t sb = smem_u32(dyn_smem);
    const int tid  = threadIdx.x;
    const int warp = tid >> 5;
    const int lane = tid & 31;
    const int g    = lane >> 2;
    const int tig  = lane & 3;
    const int b  = blockIdx.y;
    const int n0 = blockIdx.x * 128;
    const int NT = 64;

    {
        const size_t qr0 = (size_t)(b * NHW + n0);
#pragma unroll
        for (int j = 0; j < 16; j++) {
            int idx = j * 128 + tid;
            int r = idx >> 4, c4 = idx & 15;
            uint32_t doff = (uint32_t)(r * PAD * 4 + c4 * 16);
            size_t src = (qr0 + r) * 64 + c4 * 4;
            cp16(sb + OFF_QH * 4 + doff, Qhi + src);
            cp16(sb + OFF_QL * 4 + doff, Qlo + src);
        }
        prefetch_kv(sb + OFF_KV * 4, Khi, Klo, Vg, b, 0, tid);
        CP_COMMIT();
    }

    const uint32_t* Qh = (const uint32_t*)(smem + OFF_QH);
    const uint32_t* Ql = (const uint32_t*)(smem + OFF_QL);

    float Oa[2][8][4];
    float lsum[2][2];
#pragma unroll
    for (int m = 0; m < 2; m++) {
        lsum[m][0] = 0.f; lsum[m][1] = 0.f;
#pragma unroll
        for (int c = 0; c < 8; c++)
#pragma unroll
            for (int r = 0; r < 4; r++) Oa[m][c][r] = 0.f;
    }

    const int q0 = warp * 32;

    for (int i = 0; i < NT; i++) {
        __syncthreads();
        if (i + 1 < NT)
            prefetch_kv(sb + (OFF_KV + ((i + 1) & 1) * SLOT_F) * 4, Khi, Klo, Vg, b, (i + 1) * 64, tid);
        CP_COMMIT();
        if (i + 1 < NT) { CP_WAIT(1); } else { CP_WAIT(0); }
        __syncthreads();

        const float* slot = smem + OFF_KV + (i & 1) * SLOT_F;
        const uint32_t* Kh = (const uint32_t*)slot;
        const uint32_t* Kl = (const uint32_t*)(slot + KVROW_F);
        const uint32_t* Vt = (const uint32_t*)(slot + 2 * KVROW_F);

        float S[2][8][4];
#pragma unroll
        for (int m = 0; m < 2; m++)
#pragma unroll
            for (int n = 0; n < 8; n++)
#pragma unroll
                for (int r = 0; r < 4; r++) S[m][n][r] = 0.f;

#pragma unroll
        for (int k = 0; k < 8; k++) {
            uint32_t Ah[2][4], Al[2][4];
#pragma unroll
            for (int m = 0; m < 2; m++) {
                const int qr = q0 + 16 * m;
                Ah[m][0] = Qh[(qr + g) * PAD + 8 * k + tig];
                Ah[m][1] = Qh[(qr + 8 + g) * PAD + 8 * k + tig];
                Ah[m][2] = Qh[(qr + g) * PAD + 8 * k + tig + 4];
                Ah[m][3] = Qh[(qr + 8 + g) * PAD + 8 * k + tig + 4];
                Al[m][0] = Ql[(qr + g) * PAD + 8 * k + tig];
                Al[m][1] = Ql[(qr + 8 + g) * PAD + 8 * k + tig];
                Al[m][2] = Ql[(qr + g) * PAD + 8 * k + tig + 4];
                Al[m][3] = Ql[(qr + 8 + g) * PAD + 8 * k + tig + 4];
            }
#pragma unroll
            for (int n = 0; n < 8; n++) {
                const int krow = 8 * n + g;
                uint32_t bh0 = Kh[krow * PAD + 8 * k + tig];
                uint32_t bh1 = Kh[krow * PAD + 8 * k + tig + 4];
                uint32_t bl0 = Kl[krow * PAD + 8 * k + tig];
                uint32_t bl1 = Kl[krow * PAD + 8 * k + tig + 4];
                mma168(S[0][n], Ah[0], bh0, bh1);
                mma168(S[1][n], Ah[1], bh0, bh1);
                mma168(S[0][n], Ah[0], bl0, bl1);
                mma168(S[1][n], Ah[1], bl0, bl1);
                mma168(S[0][n], Al[0], bh0, bh1);
                mma168(S[1][n], Al[1], bh0, bh1);
            }
        }

#pragma unroll
        for (int m = 0; m < 2; m++) {
            float s0 = 0.f, s1 = 0.f;
#pragma unroll
            for (int n = 0; n < 8; n++) {
                float p0 = __expf(S[m][n][0]);
                float p1 = __expf(S[m][n][1]);
                float p2 = __expf(S[m][n][2]);
                float p3 = __expf(S[m][n][3]);
                S[m][n][0] = p0; S[m][n][1] = p1;
                S[m][n][2] = p2; S[m][n][3] = p3;
                s0 += p0 + p1; s1 += p2 + p3;
            }
            lsum[m][0] += s0; lsum[m][1] += s1;
        }

        const int base = lane & ~3;
        const int srcA = base | (tig >> 1);
        const int srcB = srcA + 2;
        const bool odd = (tig & 1);
#pragma unroll
        for (int n = 0; n < 8; n++) {
            uint32_t Ap[2][4];
#pragma unroll
            for (int m = 0; m < 2; m++) {
                float e0  = __shfl_sync(0xffffffffu, S[m][n][0], srcA);
                float e1  = __shfl_sync(0xffffffffu, S[m][n][1], srcA);
                float e2  = __shfl_sync(0xffffffffu, S[m][n][2], srcA);
                float e3  = __shfl_sync(0xffffffffu, S[m][n][3], srcA);
                float f0  = __shfl_sync(0xffffffffu, S[m][n][0], srcB);
                float f1  = __shfl_sync(0xffffffffu, S[m][n][1], srcB);
                float f2  = __shfl_sync(0xffffffffu, S[m][n][2], srcB);
                float f3  = __shfl_sync(0xffffffffu, S[m][n][3], srcB);
                Ap[m][0] = __float_as_uint(odd ? e1 : e0);
                Ap[m][1] = __float_as_uint(odd ? e3 : e2);
                Ap[m][2] = __float_as_uint(odd ? f1 : f0);
                Ap[m][3] = __float_as_uint(odd ? f3 : f2);
            }
#pragma unroll
            for (int c = 0; c < 8; c++) {
                uint32_t b0 = Vt[(8 * c + g) * PAD + 8 * n + tig];
                uint32_t b1 = Vt[(8 * c + g) * PAD + 8 * n + tig + 4];
                mma168(Oa[0][c], Ap[0], b0, b1);
                mma168(Oa[1][c], Ap[1], b0, b1);
            }
        }
    }

#pragma unroll
    for (int m = 0; m < 2; m++)
#pragma unroll
        for (int h = 0; h < 2; h++) {
            lsum[m][h] += __shfl_xor_sync(0xffffffffu, lsum[m][h], 1);
            lsum[m][h] += __shfl_xor_sync(0xffffffffu, lsum[m][h], 2);
            lsum[m][h] = 1.f / lsum[m][h];
        }

#pragma unroll
    for (int m = 0; m < 2; m++) {
        const int r0 = n0 + q0 + 16 * m + g;
#pragma unroll
        for (int c = 0; c < 8; c++) {
            float2 v0 = make_float2(Oa[m][c][0] * lsum[m][0], Oa[m][c][1] * lsum[m][0]);
            float2 v1 = make_float2(Oa[m][c][2] * lsum[m][1], Oa[m][c][3] * lsum[m][1]);
            *(float2*)&Og[((size_t)(b * NHW) + r0)     * 64 + 8 * c + 2 * tig] = v0;
            *(float2*)&Og[((size_t)(b * NHW) + r0 + 8) * 64 + 8 * c + 2 * tig] = v1;
        }
    }
}

// ============================================================
// proj via mma.sync, 3x tf32 split.
// out[b][o][n] = gain * sum_c W[o][c] * X[b][c][n]
// K=512 chunked by 64, double-buffered cp.async.
// smem: W chunk [64][68] x2, X chunk [64][132] x2
// ============================================================
constexpr int WCH = 64 * 68;
constexpr int XCH = 64 * 132;
#define PROJ_SMEM ((2 * WCH + 2 * XCH) * 4)   // 102400

__device__ __forceinline__ void proj_load_chunk(
    uint32_t sb, int s, const float* X, const float* W, int b, int n0, int c0, int tid)
{
    const uint32_t wdst = sb + (uint32_t)(s * WCH) * 4;
#pragma unroll
    for (int j = 0; j < 4; j++) {
        int idx = tid + j * 256;
        int o = idx >> 4, c4 = (idx & 15) << 2;
        cp16(wdst + (uint32_t)(o * 68 + c4) * 4, W + o * CC + c0 + c4);
    }
    const uint32_t xdst = sb + (uint32_t)(2 * WCH + s * XCH) * 4;
#pragma unroll
    for (int j = 0; j < 8; j++) {
        int idx = tid + j * 256;
        int cl = idx >> 5, n4 = (idx & 31) << 2;
        cp16(xdst + (uint32_t)(cl * 132 + n4) * 4,
             X + ((size_t)(b * CC + c0 + cl)) * NHW + n0 + n4);
    }
}

// mode 0: output [b][o][n] fp32 (for g / enc projections)
__global__ __launch_bounds__(256) void proj_mma0_kernel(
    const float* __restrict__ X, const float* __restrict__ W,
    float* __restrict__ out, float gain)
{
    float* smem = (float*)dyn_smem;
    const uint32_t sb = smem_u32(dyn_smem);
    const int tid  = threadIdx.x;
    const int warp = tid >> 5;
    const int lane = tid & 31;
    const int g    = lane >> 2;
    const int tig  = lane & 3;
    const int b  = blockIdx.y;
    const int n0 = blockIdx.x * 128;

    proj_load_chunk(sb, 0, X, W, b, n0, 0, tid);
    CP_COMMIT();

    float acc[4][2][4];
#pragma unroll
    for (int m = 0; m < 4; m++)
#pragma unroll
        for (int t = 0; t < 2; t++)
#pragma unroll
            for (int r = 0; r < 4; r++) acc[m][t][r] = 0.f;

    for (int kc = 0; kc < 8; kc++) {
        __syncthreads();
        if (kc + 1 < 8) proj_load_chunk(sb, (kc + 1) & 1, X, W, b, n0, (kc + 1) * 64, tid);
        CP_COMMIT();
        if (kc + 1 < 8) { CP_WAIT(1); } else { CP_WAIT(0); }
        __syncthreads();

        const float* Wc = smem + (kc & 1) * WCH;
        const float* Xc = smem + 2 * WCH + (kc & 1) * XCH;

#pragma unroll
        for (int kk = 0; kk < 8; kk++) {
            uint32_t Ah[4][4], Al[4][4];
#pragma unroll
            for (int m = 0; m < 4; m++) {
                float w0 = Wc[(16 * m + g) * 68 + 8 * kk + tig];
                float w1 = Wc[(16 * m + 8 + g) * 68 + 8 * kk + tig];
                float w2 = Wc[(16 * m + g) * 68 + 8 * kk + tig + 4];
                float w3 = Wc[(16 * m + 8 + g) * 68 + 8 * kk + tig + 4];
                float h0 = tf32hi(w0), h1 = tf32hi(w1), h2 = tf32hi(w2), h3 = tf32hi(w3);
                Ah[m][0] = __float_as_uint(h0); Ah[m][1] = __float_as_uint(h1);
                Ah[m][2] = __float_as_uint(h2); Ah[m][3] = __float_as_uint(h3);
                Al[m][0] = __float_as_uint(w0 - h0); Al[m][1] = __float_as_uint(w1 - h1);
                Al[m][2] = __float_as_uint(w2 - h2); Al[m][3] = __float_as_uint(w3 - h3);
            }
            uint32_t Bh[2][2], Bl[2][2];
#pragma unroll
            for (int t = 0; t < 2; t++) {
                float x0 = Xc[(8 * kk + tig) * 132 + 16 * warp + 8 * t + g];
                float x1 = Xc[(8 * kk + tig + 4) * 132 + 16 * warp + 8 * t + g];
                float h0 = tf32hi(x0), h1 = tf32hi(x1);
                Bh[t][0] = __float_as_uint(h0); Bh[t][1] = __float_as_uint(h1);
                Bl[t][0] = __float_as_uint(x0 - h0); Bl[t][1] = __float_as_uint(x1 - h1);
            }
#pragma unroll
            for (int m = 0; m < 4; m++)
#pragma unroll
                for (int t = 0; t < 2; t++) {
                    mma168(acc[m][t], Ah[m], Bh[t][0], Bh[t][1]);
                    mma168(acc[m][t], Ah[m], Bl[t][0], Bl[t][1]);
                    mma168(acc[m][t], Al[m], Bh[t][0], Bh[t][1]);
                }
        }
    }

#pragma unroll
    for (int m = 0; m < 4; m++)
#pragma unroll
        for (int t = 0; t < 2; t++) {
            const int o = 16 * m + g;
            const int n = n0 + 16 * warp + 8 * t + 2 * tig;
            *(float2*)&out[((size_t)(b * LL + o)) * NHW + n] =
                make_float2(acc[m][t][0] * gain, acc[m][t][1] * gain);
            *(float2*)&out[((size_t)(b * LL + o + 8)) * NHW + n] =
                make_float2(acc[m][t][2] * gain, acc[m][t][3] * gain);
        }
}

// mode 1: output hi/lo tf32 split, transposed [b][n][o] (for q / k)
__global__ __launch_bounds__(256) void proj_mma1_kernel(
    const float* __restrict__ X, const float* __restrict__ W,
    float* __restrict__ ohi, float* __restrict__ olo, float gain)
{
    float* smem = (float*)dyn_smem;
    const uint32_t sb = smem_u32(dyn_smem);
    const int tid  = threadIdx.x;
    const int warp = tid >> 5;
    const int lane = tid & 31;
    const int g    = lane >> 2;
    const int tig  = lane & 3;
    const int b  = blockIdx.y;
    const int n0 = blockIdx.x * 128;
    const int m0 = 16 * warp;    // n rows per warp

    proj_load_chunk(sb, 0, X, W, b, n0, 0, tid);
    CP_COMMIT();

    float acc[8][4];
#pragma unroll
    for (int nc = 0; nc < 8; nc++)
#pragma unroll
        for (int r = 0; r < 4; r++) acc[nc][r] = 0.f;

    for (int kc = 0; kc < 8; kc++) {
        __syncthreads();
        if (kc + 1 < 8) proj_load_chunk(sb, (kc + 1) & 1, X, W, b, n0, (kc + 1) * 64, tid);
        CP_COMMIT();
        if (kc + 1 < 8) { CP_WAIT(1); } else { CP_WAIT(0); }
        __syncthreads();

        const float* Wc = smem + (kc & 1) * WCH;
        const float* Xc = smem + 2 * WCH + (kc & 1) * XCH;

#pragma unroll
        for (int kk = 0; kk < 8; kk++) {
            // A = X^T (m = n rows)
            float x0 = Xc[(8 * kk + tig) * 132 + m0 + g];
            float x1 = Xc[(8 * kk + tig) * 132 + m0 + 8 + g];
            float x2 = Xc[(8 * kk + tig + 4) * 132 + m0 + g];
            float x3 = Xc[(8 * kk + tig + 4) * 132 + m0 + 8 + g];
            float h0 = tf32hi(x0), h1 = tf32hi(x1), h2 = tf32hi(x2), h3 = tf32hi(x3);
            uint32_t Ah[4] = {__float_as_uint(h0), __float_as_uint(h1),
                              __float_as_uint(h2), __float_as_uint(h3)};
            uint32_t Al[4] = {__float_as_uint(x0 - h0), __float_as_uint(x1 - h1),
                              __float_as_uint(x2 - h2), __float_as_uint(x3 - h3)};
#pragma unroll
            for (int nc = 0; nc < 8; nc++) {
                float w0 = Wc[(8 * nc + g) * 68 + 8 * kk + tig];
                float w1 = Wc[(8 * nc + g) * 68 + 8 * kk + tig + 4];
                float wh0 = tf32hi(w0), wh1 = tf32hi(w1);
                uint32_t bh0 = __float_as_uint(wh0), bh1 = __float_as_uint(wh1);
                uint32_t bl0 = __float_as_uint(w0 - wh0), bl1 = __float_as_uint(w1 - wh1);
                mma168(acc[nc], Ah, bh0, bh1);
                mma168(acc[nc], Ah, bl0, bl1);
                mma168(acc[nc], Al, bh0, bh1);
            }
        }
    }

#pragma unroll
    for (int nc = 0; nc < 8; nc++) {
        const int o = 8 * nc + 2 * tig;
        const size_t r0 = (size_t)(b * NHW + n0 + m0 + g);
        const size_t r1 = r0 + 8;
        float v0 = acc[nc][0] * gain, v1 = acc[nc][1] * gain;
        float v2 = acc[nc][2] * gain, v3 = acc[nc][3] * gain;
        float h0 = tf32hi(v0), h1 = tf32hi(v1), h2 = tf32hi(v2), h3 = tf32hi(v3);
        *(float2*)&ohi[r0 * 64 + o] = make_float2(h0, h1);
        *(float2*)&olo[r0 * 64 + o] = make_float2(v0 - h0, v1 - h1);
        *(float2*)&ohi[r1 * 64 + o] = make_float2(h2, h3);
        *(float2*)&olo[r1 * 64 + o] = make_float2(v2 - h2, v3 - h3);
    }
}

// ============================================================
// conv_o via mma.sync (1x tf32) + residual:
// out[b][oc][n] = gamma*0.125*sum_l Wo[oc][l]*lat[b][l][n] + addsrc
// M=512, K=64, Ntile=64. grid (64, 8), 256 thr.
// ============================================================
#define CONV_SMEM ((512 * 68 + 64 * 68) * 4)   // 156672
__global__ __launch_bounds__(256, 1) void conv_mma_kernel(
    const float* __restrict__ lat, const float* __restrict__ Wo,
    const float* __restrict__ addsrc, const float* __restrict__ gamma,
    float* __restrict__ out)
{
    float* smem = (float*)dyn_smem;
    const uint32_t sb = smem_u32(dyn_smem);
    float* Wos = smem;                 // [512][68]
    float* Ls  = smem + 512 * 68;      // [64][68]

    const int tid  = threadIdx.x;
    const int warp = tid >> 5;
    const int lane = tid & 31;
    const int g    = lane >> 2;
    const int tig  = lane & 3;
    const int b  = blockIdx.y;
    const int n0 = blockIdx.x * 64;

    // load Wo (512x64) and lat tile (64x64)
#pragma unroll
    for (int j = 0; j < 32; j++) {
        int idx = tid + j * 256;
        int oc = idx >> 4, l4 = (idx & 15) << 2;
        cp16(sb + (uint32_t)(oc * 68 + l4) * 4, Wo + oc * LL + l4);
    }
#pragma unroll
    for (int j = 0; j < 4; j++) {
        int idx = tid + j * 256;
        int cl = idx >> 4, n4 = (idx & 15) << 2;
        cp16(sb + (uint32_t)(512 * 68 + cl * 68 + n4) * 4,
             lat + ((size_t)(b * LL + cl)) * NHW + n0 + n4);
    }
    CP_COMMIT();
    CP_WAIT(0);
    __syncthreads();

    float acc[4][8][4];
#pragma unroll
    for (int m = 0; m < 4; m++)
#pragma unroll
        for (int nc = 0; nc < 8; nc++)
#pragma unroll
            for (int r = 0; r < 4; r++) acc[m][nc][r] = 0.f;

    const uint32_t* Wu = (const uint32_t*)Wos;
    const uint32_t* Lu = (const uint32_t*)Ls;

#pragma unroll
    for (int kk = 0; kk < 8; kk++) {
        uint32_t A[4][4];
#pragma unroll
        for (int m = 0; m < 4; m++) {
            const int oc = 64 * warp + 16 * m;
            A[m][0] = Wu[(oc + g) * 68 + 8 * kk + tig];
            A[m][1] = Wu[(oc + 8 + g) * 68 + 8 * kk + tig];
            A[m][2] = Wu[(oc + g) * 68 + 8 * kk + tig + 4];
            A[m][3] = Wu[(oc + 8 + g) * 68 + 8 * kk + tig + 4];
        }
#pragma unroll
        for (int nc = 0; nc < 8; nc++) {
            uint32_t b0 = Lu[(8 * kk + tig) * 68 + 8 * nc + g];
            uint32_t b1 = Lu[(8 * kk + tig + 4) * 68 + 8 * nc + g];
#pragma unroll
            for (int m = 0; m < 4; m++) mma168(acc[m][nc], A[m], b0, b1);
        }
    }

    const float coeff = gamma[0] * GAIN_O;
#pragma unroll
    for (int m = 0; m < 4; m++)
#pragma unroll
        for (int nc = 0; nc < 8; nc++) {
            const int oc = 64 * warp + 16 * m + g;
            const int n  = n0 + 8 * nc + 2 * tig;
            const size_t base0 = ((size_t)(b * CC + oc)) * NHW + n;
            const size_t base1 = base0 + (size_t)8 * NHW;
            float2 a0 = *(const float2*)&addsrc[base0];
            float2 a1 = *(const float2*)&addsrc[base1];
            *(float2*)&out[base0] = make_float2(coeff * acc[m][nc][0] + a0.x,
                                                coeff * acc[m][nc][1] + a0.y);
            *(float2*)&out[base1] = make_float2(coeff * acc[m][nc][2] + a1.x,
                                                coeff * acc[m][nc][3] + a1.y);
        }
}

// ============================================================
// MoCA attention (unchanged FFMA)
// ============================================================
#define MOCA_SMEM 223232
__global__ __launch_bounds__(256) void moca_kernel(
    const float* __restrict__ E, const float* __restrict__ Cpt, float* __restrict__ O)
{
    float* smem = (float*)dyn_smem;
    float* Ct = smem;
    float* Cs = Ct + 64 * 260;
    float* Es = Cs + 256 * 68;
    float* Pt = Es + 64 * 68;

    const int tid = threadIdx.x;
    const int b  = blockIdx.y;
    const int n0 = blockIdx.x * 64;
    const int ty = tid >> 4;
    const int tx = tid & 15;

    {
        const int c4 = (tid & 15) << 2;
#pragma unroll
        for (int p2 = 0; p2 < 16; p2++) {
            const int p = (tid >> 4) + p2 * 16;
            float4 v = *(const float4*)&Cpt[p * 64 + c4];
            *(float4*)&Cs[p * 68 + c4] = v;
            Ct[(c4 + 0) * 260 + p] = v.x; Ct[(c4 + 1) * 260 + p] = v.y;
            Ct[(c4 + 2) * 260 + p] = v.z; Ct[(c4 + 3) * 260 + p] = v.w;
        }
    }
    {
        const int nn = (tid & 15) << 2;
#pragma unroll
        for (int p2 = 0; p2 < 4; p2++) {
            const int c = (tid >> 4) + p2 * 16;
            *(float4*)&Es[c * 68 + nn] =
                *(const float4*)&E[(size_t)b * LL * NHW + (size_t)c * NHW + n0 + nn];
        }
    }
    __syncthreads();

    float s[4][16];
#pragma unroll
    for (int i = 0; i < 4; i++)
#pragma unroll
        for (int j = 0; j < 16; j++) s[i][j] = 0.f;

#pragma unroll 4
    for (int c = 0; c < 64; c++) {
        float4 q = *(float4*)&Es[c * 68 + (ty << 2)];
        float qv[4] = {q.x, q.y, q.z, q.w};
#pragma unroll
        for (int kk = 0; kk < 4; kk++) {
            float4 k = *(float4*)&Ct[c * 260 + (tx << 4) + (kk << 2)];
            float kv[4] = {k.x, k.y, k.z, k.w};
#pragma unroll
            for (int i = 0; i < 4; i++)
#pragma unroll
                for (int w = 0; w < 4; w++) s[i][(kk << 2) + w] += qv[i] * kv[w];
        }
    }

#pragma unroll
    for (int i = 0; i < 4; i++) {
        float mx = -1e30f;
#pragma unroll
        for (int j = 0; j < 16; j++) mx = fmaxf(mx, s[i][j]);
        mx = fmaxf(mx, __shfl_xor_sync(0xffffffffu, mx, 1, 16));
        mx = fmaxf(mx, __shfl_xor_sync(0xffffffffu, mx, 2, 16));
        mx = fmaxf(mx, __shfl_xor_sync(0xffffffffu, mx, 4, 16));
        mx = fmaxf(mx, __shfl_xor_sync(0xffffffffu, mx, 8, 16));
        float rs = 0.f;
#pragma unroll
        for (int j = 0; j < 16; j++) { float p = __expf(s[i][j] - mx); s[i][j] = p; rs += p; }
        rs += __shfl_xor_sync(0xffffffffu, rs, 1, 16);
        rs += __shfl_xor_sync(0xffffffffu, rs, 2, 16);
        rs += __shfl_xor_sync(0xffffffffu, rs, 4, 16);
        rs += __shfl_xor_sync(0xffffffffu, rs, 8, 16);
        const float inv = 1.f / rs;
#pragma unroll
        for (int j = 0; j < 16; j++) s[i][j] *= inv;
    }

#pragma unroll
    for (int pp = 0; pp < 16; pp++) {
        const int p = (tx << 4) + pp;
        *(float4*)&Pt[p * 68 + (ty << 2)] = make_float4(s[0][pp], s[1][pp], s[2][pp], s[3][pp]);
    }
    __syncthreads();

    float o_acc[4][4];
#pragma unroll
    for (int i = 0; i < 4; i++)
#pragma unroll
        for (int j = 0; j < 4; j++) o_acc[i][j] = 0.f;

#pragma unroll 8
    for (int p = 0; p < 256; p++) {
        float4 pr = *(float4*)&Pt[p * 68 + (ty << 2)];
        float4 v  = *(float4*)&Cs[p * 68 + (tx << 2)];
        float pv[4] = {pr.x, pr.y, pr.z, pr.w};
        float vv[4] = {v.x, v.y, v.z, v.w};
#pragma unroll
        for (int i = 0; i < 4; i++)
#pragma unroll
            for (int j = 0; j < 4; j++) o_acc[i][j] += pv[i] * vv[j];
    }
#pragma unroll
    for (int i = 0; i < 4; i++) {
        const int n = n0 + (ty << 2) + i;
        *(float4*)&O[(size_t)b * NHW * LL + (size_t)n * LL + (tx << 2)] =
            make_float4(o_acc[i][0], o_acc[i][1], o_acc[i][2], o_acc[i][3]);
    }
}

// ============================================================
extern "C" void kernel_launch(void* const* d_in, const int* in_sizes, int n_in,
                              void* d_out, int out_size)
{
    (void)in_sizes; (void)n_in; (void)out_size;
    const float* fm         = (const float*)d_in[0];
    const float* concepts   = (const float*)d_in[1];
    const float* w_theta    = (const float*)d_in[2];
    const float* w_phi      = (const float*)d_in[3];
    const float* w_g        = (const float*)d_in[4];
    const float* w_o        = (const float*)d_in[5];
    const float* gamma_sa   = (const float*)d_in[6];
    const float* gamma_moca = (const float*)d_in[7];
    float* out = (float*)d_out;

    float *qhi, *qlo, *khi, *klo, *gv, *lat, *sa, *enc, *lat2;
    cudaGetSymbolAddress((void**)&qhi, g_qhi);
    cudaGetSymbolAddress((void**)&qlo, g_qlo);
    cudaGetSymbolAddress((void**)&khi, g_khi);
    cudaGetSymbolAddress((void**)&klo, g_klo);
    cudaGetSymbolAddress((void**)&gv,  g_gv);
    cudaGetSymbolAddress((void**)&lat, g_lat);
    cudaGetSymbolAddress((void**)&sa,  g_sa);
    cudaGetSymbolAddress((void**)&enc, g_enc);
    cudaGetSymbolAddress((void**)&lat2, g_lat2);

    cudaFuncSetAttribute(flash_mma_kernel, cudaFuncAttributeMaxDynamicSharedMemorySize, FT_SMEM);
    cudaFuncSetAttribute(proj_mma0_kernel, cudaFuncAttributeMaxDynamicSharedMemorySize, PROJ_SMEM);
    cudaFuncSetAttribute(proj_mma1_kernel, cudaFuncAttributeMaxDynamicSharedMemorySize, PROJ_SMEM);
    cudaFuncSetAttribute(conv_mma_kernel,  cudaFuncAttributeMaxDynamicSharedMemorySize, CONV_SMEM);
    cudaFuncSetAttribute(moca_kernel,      cudaFuncAttributeMaxDynamicSharedMemorySize, MOCA_SMEM);

    const dim3 pgrid(32, 8);
    proj_mma1_kernel<<<pgrid, 256, PROJ_SMEM>>>(fm, w_theta, qhi, qlo, GAIN_IN);
    proj_mma1_kernel<<<pgrid, 256, PROJ_SMEM>>>(fm, w_phi,   khi, klo, GAIN_IN);
    proj_mma0_kernel<<<pgrid, 256, PROJ_SMEM>>>(fm, w_g,     gv,  GAIN_IN);
    flash_mma_kernel<<<dim3(32, 8), 128, FT_SMEM>>>(qhi, qlo, khi, klo, gv, lat);
    conv_mma_kernel<<<dim3(64, 8), 256, CONV_SMEM>>>(lat, w_o, fm, gamma_sa, sa);
    proj_mma0_kernel<<<pgrid, 256, PROJ_SMEM>>>(sa, w_theta, enc, GAIN_IN);
    moca_kernel<<<dim3(64, 8), 256, MOCA_SMEM>>>(enc, concepts, lat2);
    conv_mma_kernel<<<dim3(64, 8), 256, CONV_SMEM>>>(lat2, w_o, sa, gamma_moca, out);
}